// round 14
// baseline (speedup 1.0000x reference)
#include <cuda_runtime.h>
#include <math.h>
#include <stdint.h>

#define BSZ 16
#define SEQ 512
#define DM 1024
#define NH 16
#define HDIM 64
#define DFF 4096
#define MROWS (BSZ * SEQ)  // 8192
#define QKVD (3 * DM)      // 3072

// ---------------- scratch (device globals; no cudaMalloc allowed) ----------
__device__ __align__(16) int8_t g_wq1[12582912];   // weight limb1 (all 4 mats)
__device__ __align__(16) int8_t g_wq2[12582912];   // weight limb2
__device__ float g_sw[9216];                        // weight row scales
__device__ __align__(16) int8_t g_xq1[(size_t)MROWS * DM];
__device__ __align__(16) int8_t g_xq2[(size_t)MROWS * DM];
__device__ float g_sx[MROWS];
__device__ __align__(16) int8_t g_fq1[(size_t)MROWS * DFF];
__device__ __align__(16) int8_t g_fq2[(size_t)MROWS * DFF];
__device__ float g_sf[MROWS];
__device__ float g_qkv[(size_t)MROWS * QKVD];      // 100 MB
__device__ float g_attn[(size_t)MROWS * DM];       // 33 MB
__device__ float g_ffn[(size_t)MROWS * DFF];       // 134 MB

// ---------------- PTX helpers ----------------------------------------------
__device__ __forceinline__ uint32_t s2u(const void* p) {
    uint32_t a;
    asm("{ .reg .u64 t; cvta.to.shared.u64 t, %1; cvt.u32.u64 %0, t; }"
        : "=r"(a) : "l"(p));
    return a;
}
__device__ __forceinline__ void cp_async16(uint32_t dst, const void* src) {
    asm volatile("cp.async.cg.shared.global [%0], [%1], 16;"
                 :: "r"(dst), "l"(src) : "memory");
}
__device__ __forceinline__ void cp_commit() {
    asm volatile("cp.async.commit_group;" ::: "memory");
}
template <int N>
__device__ __forceinline__ void cp_wait() {
    asm volatile("cp.async.wait_group %0;" :: "n"(N) : "memory");
}
#define LDSM4(d, a) \
    asm volatile("ldmatrix.sync.aligned.m8n8.x4.shared.b16 {%0,%1,%2,%3}, [%4];" \
                 : "=r"((d)[0]), "=r"((d)[1]), "=r"((d)[2]), "=r"((d)[3]) : "r"(a))
// IMMA m16n8k32 s8*s8 -> s32, accumulate in place
#define IMMA(c, a, b0, b1) \
    asm volatile( \
        "mma.sync.aligned.m16n8k32.row.col.s32.s8.s8.s32 " \
        "{%0,%1,%2,%3},{%4,%5,%6,%7},{%8,%9},{%0,%1,%2,%3};" \
        : "+r"((c)[0]), "+r"((c)[1]), "+r"((c)[2]), "+r"((c)[3]) \
        : "r"((a)[0]), "r"((a)[1]), "r"((a)[2]), "r"((a)[3]), \
          "r"(b0), "r"(b1))

// SMEM tile: 128 rows x 64 bytes data, 80-byte row stride.
// 80 = 5*16 keeps every ldmatrix address 16B-aligned; 80*r mod 128 cycles
// through all eight 16B chunks over any 8 rows -> conflict-free ldmatrix.
#define ROWB 80
#define TILEI (128 * ROWB)               // 10240
#define STAGEB (4 * TILEI)               // 40960 (Aq1,Aq2,Bq1,Bq2)
#define NSTAGE 4
#define SMEM_BYTES (NSTAGE * STAGEB)     // 163840

__device__ __forceinline__ float gelu_f(float v) {
    return 0.5f * v * (1.f + erff(v * 0.70710678118654752f));
}

// quantize 1 float (already scaled by inv) into two int8 limbs
__device__ __forceinline__ void q2limb(float v, signed char& c1, signed char& c2) {
    float a = rintf(v * 0.0078125f);           // v/128, |a| <= 127
    float b = rintf(fmaf(-128.f, a, v));       // residual in [-64,64]
    c1 = (signed char)(int)a;
    c2 = (signed char)(int)b;
}

// ---------------- row-wise quantizer: fp32 [rows,cols] -> q1,q2 + scale ----
// grid = rows, block = 256. cols in {1024, 4096}.
__global__ void quant_rows(const float* __restrict__ in, int cols,
                           int8_t* __restrict__ q1, int8_t* __restrict__ q2,
                           float* __restrict__ scale) {
    int row = blockIdx.x, tid = threadIdx.x;
    int nv = cols >> 10;  // float4s per thread
    const float4* src = (const float4*)(in + (size_t)row * cols);
    float4 buf[4];
    float mx = 0.f;
    for (int i = 0; i < nv; i++) {
        buf[i] = src[i * 256 + tid];
        mx = fmaxf(mx, fmaxf(fmaxf(fabsf(buf[i].x), fabsf(buf[i].y)),
                             fmaxf(fabsf(buf[i].z), fabsf(buf[i].w))));
    }
    __shared__ float red[8];
#pragma unroll
    for (int off = 16; off > 0; off >>= 1)
        mx = fmaxf(mx, __shfl_xor_sync(0xffffffffu, mx, off));
    if ((tid & 31) == 0) red[tid >> 5] = mx;
    __syncthreads();
    if (tid < 32) {
        float m2 = (tid < 8) ? red[tid] : 0.f;
#pragma unroll
        for (int off = 4; off > 0; off >>= 1)
            m2 = fmaxf(m2, __shfl_xor_sync(0xffffffffu, m2, off));
        if (tid == 0) red[0] = m2;
    }
    __syncthreads();
    float rowmax = red[0];
    float inv = rowmax > 0.f ? 16256.f / rowmax : 0.f;
    if (tid == 0) scale[row] = rowmax > 0.f ? rowmax * (1.f / 16256.f) : 0.f;
    char4* d1 = (char4*)(q1 + (size_t)row * cols);
    char4* d2 = (char4*)(q2 + (size_t)row * cols);
    for (int i = 0; i < nv; i++) {
        float4 v = buf[i];
        char4 a, b;
        q2limb(v.x * inv, a.x, b.x);
        q2limb(v.y * inv, a.y, b.y);
        q2limb(v.z * inv, a.z, b.z);
        q2limb(v.w * inv, a.w, b.w);
        d1[i * 256 + tid] = a;
        d2[i * 256 + tid] = b;
    }
}

// ---------------- LayerNorm fused with quantization ------------------------
__global__ void ln_quant(const float* __restrict__ x, const float* __restrict__ w,
                         const float* __restrict__ b, int8_t* __restrict__ q1,
                         int8_t* __restrict__ q2, float* __restrict__ scale) {
    int row = blockIdx.x, tid = threadIdx.x;
    const float4* xr = (const float4*)(x + (size_t)row * DM);
    float4 v = xr[tid];
    float s = v.x + v.y + v.z + v.w;
    float s2 = v.x * v.x + v.y * v.y + v.z * v.z + v.w * v.w;
    __shared__ float red[16];
#pragma unroll
    for (int off = 16; off > 0; off >>= 1) {
        s += __shfl_xor_sync(0xffffffffu, s, off);
        s2 += __shfl_xor_sync(0xffffffffu, s2, off);
    }
    int wid = tid >> 5;
    if ((tid & 31) == 0) { red[wid] = s; red[8 + wid] = s2; }
    __syncthreads();
    if (tid < 32) {
        s = (tid < 8) ? red[tid] : 0.f;
        s2 = (tid < 8) ? red[8 + tid] : 0.f;
#pragma unroll
        for (int off = 4; off > 0; off >>= 1) {
            s += __shfl_xor_sync(0xffffffffu, s, off);
            s2 += __shfl_xor_sync(0xffffffffu, s2, off);
        }
        if (tid == 0) {
            float mu = s * (1.f / DM);
            float var = s2 * (1.f / DM) - mu * mu;
            red[0] = mu;
            red[1] = rsqrtf(var + 1e-5f);
        }
    }
    __syncthreads();
    float mu = red[0], rstd = red[1];
    float4 wv = ((const float4*)w)[tid];
    float4 bv = ((const float4*)b)[tid];
    float4 o;
    o.x = (v.x - mu) * rstd * wv.x + bv.x;
    o.y = (v.y - mu) * rstd * wv.y + bv.y;
    o.z = (v.z - mu) * rstd * wv.z + bv.z;
    o.w = (v.w - mu) * rstd * wv.w + bv.w;
    // row max of |o|
    float mx = fmaxf(fmaxf(fabsf(o.x), fabsf(o.y)), fmaxf(fabsf(o.z), fabsf(o.w)));
    __shared__ float redm[8];
#pragma unroll
    for (int off = 16; off > 0; off >>= 1)
        mx = fmaxf(mx, __shfl_xor_sync(0xffffffffu, mx, off));
    if ((tid & 31) == 0) redm[wid] = mx;
    __syncthreads();
    if (tid < 32) {
        float m2 = (tid < 8) ? redm[tid] : 0.f;
#pragma unroll
        for (int off = 4; off > 0; off >>= 1)
            m2 = fmaxf(m2, __shfl_xor_sync(0xffffffffu, m2, off));
        if (tid == 0) redm[0] = m2;
    }
    __syncthreads();
    float rowmax = redm[0];
    float inv = rowmax > 0.f ? 16256.f / rowmax : 0.f;
    if (tid == 0) scale[row] = rowmax > 0.f ? rowmax * (1.f / 16256.f) : 0.f;
    char4 a, bq;
    q2limb(o.x * inv, a.x, bq.x);
    q2limb(o.y * inv, a.y, bq.y);
    q2limb(o.z * inv, a.z, bq.z);
    q2limb(o.w * inv, a.w, bq.w);
    ((char4*)(q1 + (size_t)row * DM))[tid] = a;
    ((char4*)(q2 + (size_t)row * DM))[tid] = bq;
}

// ---------------- int8 two-limb GEMM via IMMA ------------------------------
// C[m,n] = sA[m]*sB[n]*(16384*sum(q1a*q1b) + 128*sum(q1a*q2b + q2a*q1b))
// (+bias, EPI). CTA tile 128x128, BK=64, 256 thr, warp tile 64x32.
// EPI: 0 = bias -> Cf; 1 = gelu(bias+acc) -> Cf; 2 = res+bias+acc -> Cf
template <int EPI>
__global__ void __launch_bounds__(256, 1) gemm_i8(
    const int8_t* __restrict__ Aq1, const int8_t* __restrict__ Aq2,
    const int8_t* __restrict__ Wq1, const int8_t* __restrict__ Wq2,
    const float* __restrict__ sA, const float* __restrict__ sB,
    const float* __restrict__ bias, const float* __restrict__ res,
    float* __restrict__ Cf, int N, int K) {
    extern __shared__ char smem[];
    uint32_t sbase = s2u(smem);
    int tid = threadIdx.x;
    int w = tid >> 5, lane = tid & 31;
    int bm = blockIdx.y, bn = blockIdx.x;
    int mbase = (w & 1) * 64, nbase = (w >> 1) * 32;

    const int8_t* tsrc[4];
    tsrc[0] = Aq1 + (size_t)bm * 128 * K;
    tsrc[1] = Aq2 + (size_t)bm * 128 * K;
    tsrc[2] = Wq1 + (size_t)bn * 128 * K;
    tsrc[3] = Wq2 + (size_t)bn * 128 * K;

    int g = lane >> 3, lr = lane & 7;
    uint32_t offA = (uint32_t)((mbase + (g & 1) * 8 + lr) * ROWB + (g >> 1) * 16);
    uint32_t offB = (uint32_t)((nbase + (g >> 1) * 8 + lr) * ROWB + (g & 1) * 16);

    int acc1[4][4][4], acc2[4][4][4];
#pragma unroll
    for (int mt = 0; mt < 4; mt++)
#pragma unroll
        for (int nt = 0; nt < 4; nt++)
#pragma unroll
            for (int u = 0; u < 4; u++) { acc1[mt][nt][u] = 0; acc2[mt][nt][u] = 0; }

    int NK = K >> 6;  // BK = 64 bytes of K per stage

    // stage loader: 4 tiles of 128 rows x 64B; 512 chunks/tile; 2 per thread
#define LOAD_STAGE(s_, buf_)                                                   \
    do {                                                                       \
        uint32_t sb_ = sbase + (buf_) * STAGEB;                                \
        int k0_ = (s_) << 6;                                                   \
        _Pragma("unroll")                                                      \
        for (int t = 0; t < 4; t++) {                                          \
            _Pragma("unroll")                                                  \
            for (int u = 0; u < 2; u++) {                                      \
                int idx = tid + u * 256;                                       \
                int r = idx >> 2, c = idx & 3;                                 \
                cp_async16(sb_ + t * TILEI + r * ROWB + c * 16,                \
                           tsrc[t] + (size_t)r * K + k0_ + c * 16);            \
            }                                                                  \
        }                                                                      \
    } while (0)

    // prologue: stages 0..2
#pragma unroll
    for (int s = 0; s < NSTAGE - 1; s++) {
        LOAD_STAGE(s, s);
        cp_commit();
    }

    for (int k = 0; k < NK; k++) {
        cp_wait<NSTAGE - 2>();
        __syncthreads();

        if (k + NSTAGE - 1 < NK) LOAD_STAGE(k + NSTAGE - 1, (k + NSTAGE - 1) & (NSTAGE - 1));
        cp_commit();

        uint32_t sb = sbase + (k & (NSTAGE - 1)) * STAGEB;
        uint32_t aA1 = sb + offA, aA2 = sb + TILEI + offA;
        uint32_t aB1 = sb + 2 * TILEI + offB, aB2 = sb + 3 * TILEI + offB;

#pragma unroll
        for (int ks = 0; ks < 2; ks++) {
            uint32_t ko = ks * 32;
            uint32_t a1[4][4], a2[4][4];
#pragma unroll
            for (int mt = 0; mt < 4; mt++) {
                LDSM4(a1[mt], aA1 + ko + mt * (16 * ROWB));
                LDSM4(a2[mt], aA2 + ko + mt * (16 * ROWB));
            }
#pragma unroll
            for (int j = 0; j < 2; j++) {
                uint32_t b1[4], b2[4];
                LDSM4(b1, aB1 + ko + j * (16 * ROWB));
                LDSM4(b2, aB2 + ko + j * (16 * ROWB));
#pragma unroll
                for (int mt = 0; mt < 4; mt++) {
                    IMMA(acc1[mt][2 * j], a1[mt], b1[0], b1[1]);
                    IMMA(acc2[mt][2 * j], a1[mt], b2[0], b2[1]);
                    IMMA(acc2[mt][2 * j], a2[mt], b1[0], b1[1]);
                    IMMA(acc1[mt][2 * j + 1], a1[mt], b1[2], b1[3]);
                    IMMA(acc2[mt][2 * j + 1], a1[mt], b2[2], b2[3]);
                    IMMA(acc2[mt][2 * j + 1], a2[mt], b1[2], b1[3]);
                }
            }
        }
    }
#undef LOAD_STAGE

    // ---------------- epilogue ----------------
    int l4 = lane >> 2, l2 = (lane & 3) * 2;
#pragma unroll
    for (int mt = 0; mt < 4; mt++) {
        int row = bm * 128 + mbase + mt * 16 + l4;
        float sa0 = sA[row], sa1 = sA[row + 8];
#pragma unroll
        for (int nt = 0; nt < 4; nt++) {
            int col = bn * 128 + nbase + nt * 8 + l2;
            float2 sb2 = *(const float2*)(sB + col);
            float2 bv = *(const float2*)(bias + col);
            float t0 = fmaf(16384.f, (float)acc1[mt][nt][0], 128.f * (float)acc2[mt][nt][0]);
            float t1 = fmaf(16384.f, (float)acc1[mt][nt][1], 128.f * (float)acc2[mt][nt][1]);
            float t2 = fmaf(16384.f, (float)acc1[mt][nt][2], 128.f * (float)acc2[mt][nt][2]);
            float t3 = fmaf(16384.f, (float)acc1[mt][nt][3], 128.f * (float)acc2[mt][nt][3]);
            float v0 = sa0 * sb2.x * t0 + bv.x;
            float v1 = sa0 * sb2.y * t1 + bv.y;
            float v2 = sa1 * sb2.x * t2 + bv.x;
            float v3 = sa1 * sb2.y * t3 + bv.y;
            size_t p0 = (size_t)row * N + col;
            size_t p1 = (size_t)(row + 8) * N + col;
            if (EPI == 2) {
                float2 rv0 = *(const float2*)(res + p0);
                float2 rv1 = *(const float2*)(res + p1);
                v0 += rv0.x; v1 += rv0.y; v2 += rv1.x; v3 += rv1.y;
            }
            if (EPI == 1) {
                v0 = gelu_f(v0); v1 = gelu_f(v1);
                v2 = gelu_f(v2); v3 = gelu_f(v3);
            }
            *(float2*)(Cf + p0) = make_float2(v0, v1);
            *(float2*)(Cf + p1) = make_float2(v2, v3);
        }
    }
}

// ---------------- Flash-style attention (fp32 in/out) -----------------------
__global__ __launch_bounds__(256, 4) void attn_kernel(
    const float* __restrict__ qkv, const float* __restrict__ rel_bias,
    float* __restrict__ attn_out) {
    __shared__ float Qt[64 * 64];
    __shared__ float KVs[64 * 64];
    __shared__ float Ps[64 * 64];
    int tid = threadIdx.x;
    int tx = tid & 15, ty = tid >> 4;
    int qt = blockIdx.x, h = blockIdx.y, b = blockIdx.z;

    const float* qbase = qkv + (size_t)(b * SEQ + qt * 64) * QKVD + h * HDIM;
    const float* kbase = qkv + (size_t)(b * SEQ) * QKVD + DM + h * HDIM;
    const float* vbase = kbase + DM;
    const float* biasrow = rel_bias + h * (2 * SEQ - 1);

    {
        int r = tid >> 2;
        int d0 = (tid & 3) << 4;
        const float* src = qbase + (size_t)r * QKVD + d0;
#pragma unroll
        for (int u = 0; u < 16; u += 4) {
            float4 v = *(const float4*)(src + u);
            Qt[(d0 + u + 0) * 64 + r] = v.x;
            Qt[(d0 + u + 1) * 64 + r] = v.y;
            Qt[(d0 + u + 2) * 64 + r] = v.z;
            Qt[(d0 + u + 3) * 64 + r] = v.w;
        }
    }

    float m[4], l[4], o[4][4];
#pragma unroll
    for (int i = 0; i < 4; i++) {
        m[i] = -1e30f;
        l[i] = 0.f;
#pragma unroll
        for (int c = 0; c < 4; c++) o[i][c] = 0.f;
    }

    for (int kt = 0; kt < 8; kt++) {
        __syncthreads();
        {
            int r = tid >> 2;
            int d0 = (tid & 3) << 4;
            const float* src = kbase + (size_t)(kt * 64 + r) * QKVD + d0;
#pragma unroll
            for (int u = 0; u < 16; u += 4) {
                float4 v = *(const float4*)(src + u);
                KVs[(d0 + u + 0) * 64 + r] = v.x;
                KVs[(d0 + u + 1) * 64 + r] = v.y;
                KVs[(d0 + u + 2) * 64 + r] = v.z;
                KVs[(d0 + u + 3) * 64 + r] = v.w;
            }
        }
        __syncthreads();

        float s[4][4];
#pragma unroll
        for (int i = 0; i < 4; i++)
#pragma unroll
            for (int j = 0; j < 4; j++) s[i][j] = 0.f;
#pragma unroll 16
        for (int d = 0; d < 64; d++) {
            float4 a = *(const float4*)&Qt[d * 64 + ty * 4];
            float4 bq = *(const float4*)&KVs[d * 64 + tx * 4];
            float aa[4] = {a.x, a.y, a.z, a.w};
            float bb[4] = {bq.x, bq.y, bq.z, bq.w};
#pragma unroll
            for (int i = 0; i < 4; i++)
#pragma unroll
                for (int j = 0; j < 4; j++) s[i][j] += aa[i] * bb[j];
        }

        int qg = qt * 64 + ty * 4;
        int kg = kt * 64 + tx * 4;
#pragma unroll
        for (int i = 0; i < 4; i++)
#pragma unroll
            for (int j = 0; j < 4; j++)
                s[i][j] = s[i][j] * 0.125f +
                          __ldg(&biasrow[(qg + i) - (kg + j) + (SEQ - 1)]);

        float mt[4];
#pragma unroll
        for (int i = 0; i < 4; i++) {
            mt[i] = fmaxf(fmaxf(s[i][0], s[i][1]), fmaxf(s[i][2], s[i][3]));
#pragma unroll
            for (int off = 8; off > 0; off >>= 1)
                mt[i] = fmaxf(mt[i], __shfl_xor_sync(0xffffffffu, mt[i], off, 16));
        }
        float fac[4];
#pragma unroll
        for (int i = 0; i < 4; i++) {
            float mn = fmaxf(m[i], mt[i]);
            fac[i] = __expf(m[i] - mn);
            m[i] = mn;
        }
        float rs[4];
#pragma unroll
        for (int i = 0; i < 4; i++) {
            rs[i] = 0.f;
#pragma unroll
            for (int j = 0; j < 4; j++) {
                float p = __expf(s[i][j] - m[i]);
                s[i][j] = p;
                rs[i] += p;
            }
#pragma unroll
            for (int off = 8; off > 0; off >>= 1)
                rs[i] += __shfl_xor_sync(0xffffffffu, rs[i], off, 16);
            l[i] = l[i] * fac[i] + rs[i];
#pragma unroll
            for (int c = 0; c < 4; c++) o[i][c] *= fac[i];
        }
#pragma unroll
        for (int i = 0; i < 4; i++)
            *(float4*)&Ps[(ty * 4 + i) * 64 + tx * 4] =
                make_float4(s[i][0], s[i][1], s[i][2], s[i][3]);
        __syncthreads();

        {
            int r = tid >> 2;
            int d0 = (tid & 3) << 4;
            const float* src = vbase + (size_t)(kt * 64 + r) * QKVD + d0;
#pragma unroll
            for (int u = 0; u < 16; u += 4)
                *(float4*)&KVs[r * 64 + d0 + u] = *(const float4*)(src + u);
        }
        __syncthreads();

#pragma unroll 16
        for (int j = 0; j < 64; j++) {
            float pa[4];
#pragma unroll
            for (int i = 0; i < 4; i++) pa[i] = Ps[(ty * 4 + i) * 64 + j];
            float4 vb = *(const float4*)&KVs[j * 64 + tx * 4];
            float vv[4] = {vb.x, vb.y, vb.z, vb.w};
#pragma unroll
            for (int i = 0; i < 4; i++)
#pragma unroll
                for (int c = 0; c < 4; c++) o[i][c] += pa[i] * vv[c];
        }
    }

    float* obase = attn_out + (size_t)(b * SEQ + qt * 64) * DM + h * HDIM;
#pragma unroll
    for (int i = 0; i < 4; i++) {
        float inv = 1.f / l[i];
        float4 rr = make_float4(o[i][0] * inv, o[i][1] * inv, o[i][2] * inv,
                                o[i][3] * inv);
        *(float4*)&obase[(size_t)(ty * 4 + i) * DM + tx * 4] = rr;
    }
}

// ---------------- launch ---------------------------------------------------
extern "C" void kernel_launch(void* const* d_in, const int* in_sizes, int n_in,
                              void* d_out, int out_size) {
    const float* x = (const float*)d_in[0];
    const float* in_w = (const float*)d_in[1];
    const float* in_b = (const float*)d_in[2];
    const float* out_w = (const float*)d_in[3];
    const float* out_b = (const float*)d_in[4];
    const float* rel_bias = (const float*)d_in[5];
    const float* w1 = (const float*)d_in[6];
    const float* b1 = (const float*)d_in[7];
    const float* w2 = (const float*)d_in[8];
    const float* b2 = (const float*)d_in[9];
    const float* ln1w = (const float*)d_in[10];
    const float* ln1b = (const float*)d_in[11];
    const float* ln2w = (const float*)d_in[12];
    const float* ln2b = (const float*)d_in[13];
    float* out = (float*)d_out;

    int8_t *wq1, *wq2, *xq1, *xq2, *fq1, *fq2;
    float *sw, *sx, *sf, *qkv, *attn, *ffn;
    cudaGetSymbolAddress((void**)&wq1, g_wq1);
    cudaGetSymbolAddress((void**)&wq2, g_wq2);
    cudaGetSymbolAddress((void**)&sw, g_sw);
    cudaGetSymbolAddress((void**)&xq1, g_xq1);
    cudaGetSymbolAddress((void**)&xq2, g_xq2);
    cudaGetSymbolAddress((void**)&sx, g_sx);
    cudaGetSymbolAddress((void**)&fq1, g_fq1);
    cudaGetSymbolAddress((void**)&fq2, g_fq2);
    cudaGetSymbolAddress((void**)&sf, g_sf);
    cudaGetSymbolAddress((void**)&qkv, g_qkv);
    cudaGetSymbolAddress((void**)&attn, g_attn);
    cudaGetSymbolAddress((void**)&ffn, g_ffn);

    cudaFuncSetAttribute(gemm_i8<0>, cudaFuncAttributeMaxDynamicSharedMemorySize, SMEM_BYTES);
    cudaFuncSetAttribute(gemm_i8<1>, cudaFuncAttributeMaxDynamicSharedMemorySize, SMEM_BYTES);
    cudaFuncSetAttribute(gemm_i8<2>, cudaFuncAttributeMaxDynamicSharedMemorySize, SMEM_BYTES);

    const size_t OFF_INW = 0;            // 3072 rows x 1024
    const size_t OFF_OUTW = 3145728;     // 1024 rows x 1024
    const size_t OFF_W1 = 4194304;       // 4096 rows x 1024
    const size_t OFF_W2 = 8388608;       // 1024 rows x 4096

    // quantize weights (per output-feature row)
    quant_rows<<<3072, 256>>>(in_w, 1024, wq1 + OFF_INW, wq2 + OFF_INW, sw + 0);
    quant_rows<<<1024, 256>>>(out_w, 1024, wq1 + OFF_OUTW, wq2 + OFF_OUTW, sw + 3072);
    quant_rows<<<4096, 256>>>(w1, 1024, wq1 + OFF_W1, wq2 + OFF_W1, sw + 4096);
    quant_rows<<<1024, 256>>>(w2, 4096, wq1 + OFF_W2, wq2 + OFF_W2, sw + 8192);

    // 1. LN1 + quantize
    ln_quant<<<MROWS, 256>>>(x, ln1w, ln1b, xq1, xq2, sx);
    // 2. qkv = xn @ in_proj_w^T + b
    gemm_i8<0><<<dim3(QKVD / 128, MROWS / 128), 256, SMEM_BYTES>>>(
        xq1, xq2, wq1 + OFF_INW, wq2 + OFF_INW, sx, sw + 0, in_b, nullptr, qkv,
        QKVD, DM);
    // 3. attention (fp32)
    attn_kernel<<<dim3(SEQ / 64, NH, BSZ), 256>>>(qkv, rel_bias, attn);
    // 3b. quantize attention output
    quant_rows<<<MROWS, 256>>>(attn, 1024, xq1, xq2, sx);
    // 4. out = x + attn @ out_w^T + b
    gemm_i8<2><<<dim3(DM / 128, MROWS / 128), 256, SMEM_BYTES>>>(
        xq1, xq2, wq1 + OFF_OUTW, wq2 + OFF_OUTW, sx, sw + 3072, out_b, x, out,
        DM, DM);
    // 5. LN2 + quantize
    ln_quant<<<MROWS, 256>>>(out, ln2w, ln2b, xq1, xq2, sx);
    // 6. ffn = gelu(xn @ w1^T + b1)  (fp32 out)
    gemm_i8<1><<<dim3(DFF / 128, MROWS / 128), 256, SMEM_BYTES>>>(
        xq1, xq2, wq1 + OFF_W1, wq2 + OFF_W1, sx, sw + 4096, b1, nullptr, ffn,
        DFF, DM);
    // 6b. quantize ffn activations
    quant_rows<<<MROWS, 256>>>(ffn, 4096, fq1, fq2, sf);
    // 7. out = out + ffn @ w2^T + b2
    gemm_i8<2><<<dim3(DM / 128, MROWS / 128), 256, SMEM_BYTES>>>(
        fq1, fq2, wq1 + OFF_W2, wq2 + OFF_W2, sf, sw + 8192, b2, out, out,
        DM, DFF);
}

// round 16
// speedup vs baseline: 2.6549x; 2.6549x over previous
#include <cuda_runtime.h>
#include <cuda_bf16.h>
#include <cuda_fp16.h>
#include <math.h>
#include <stdint.h>

#define BSZ 16
#define SEQ 512
#define DM 1024
#define NH 16
#define HDIM 64
#define DFF 4096
#define MROWS (BSZ * SEQ)  // 8192
#define QKVD (3 * DM)      // 3072

// ---------------- scratch (device globals; no cudaMalloc allowed) ----------
__device__ __align__(16) __nv_bfloat16 g_wh[12582912];            // weights hi
__device__ __align__(16) __nv_bfloat16 g_wl[12582912];            // weights lo
__device__ __align__(16) __nv_bfloat16 g_xh[(size_t)MROWS * DM];  // act pair
__device__ __align__(16) __nv_bfloat16 g_xl[(size_t)MROWS * DM];
__device__ __align__(16) __nv_bfloat16 g_ah[(size_t)MROWS * DFF]; // ffn pair
__device__ __align__(16) __nv_bfloat16 g_al[(size_t)MROWS * DFF];
__device__ float g_qkv[(size_t)MROWS * QKVD];

// ---------------- PTX helpers ----------------------------------------------
__device__ __forceinline__ uint32_t s2u(const void* p) {
    uint32_t a;
    asm("{ .reg .u64 t; cvta.to.shared.u64 t, %1; cvt.u32.u64 %0, t; }"
        : "=r"(a) : "l"(p));
    return a;
}
__device__ __forceinline__ void cp_async16(uint32_t dst, const void* src) {
    asm volatile("cp.async.cg.shared.global [%0], [%1], 16;"
                 :: "r"(dst), "l"(src) : "memory");
}
__device__ __forceinline__ void cp_commit() {
    asm volatile("cp.async.commit_group;" ::: "memory");
}
template <int N>
__device__ __forceinline__ void cp_wait() {
    asm volatile("cp.async.wait_group %0;" :: "n"(N) : "memory");
}
#define LDSM4(d, a) \
    asm volatile("ldmatrix.sync.aligned.m8n8.x4.shared.b16 {%0,%1,%2,%3}, [%4];" \
                 : "=r"((d)[0]), "=r"((d)[1]), "=r"((d)[2]), "=r"((d)[3]) : "r"(a))
#define LDSM4T(d, a) \
    asm volatile("ldmatrix.sync.aligned.m8n8.x4.trans.shared.b16 {%0,%1,%2,%3}, [%4];" \
                 : "=r"((d)[0]), "=r"((d)[1]), "=r"((d)[2]), "=r"((d)[3]) : "r"(a))
#define MMA16816(c, a, b0, b1) \
    asm volatile( \
        "mma.sync.aligned.m16n8k16.row.col.f32.bf16.bf16.f32 " \
        "{%0,%1,%2,%3},{%4,%5,%6,%7},{%8,%9},{%0,%1,%2,%3};" \
        : "+f"((c)[0]), "+f"((c)[1]), "+f"((c)[2]), "+f"((c)[3]) \
        : "r"((a)[0]), "r"((a)[1]), "r"((a)[2]), "r"((a)[3]), \
          "r"(b0), "r"(b1))
#define MMAF16(c, a, b0, b1) \
    asm volatile( \
        "mma.sync.aligned.m16n8k16.row.col.f32.f16.f16.f32 " \
        "{%0,%1,%2,%3},{%4,%5,%6,%7},{%8,%9},{%0,%1,%2,%3};" \
        : "+f"((c)[0]), "+f"((c)[1]), "+f"((c)[2]), "+f"((c)[3]) \
        : "r"((a)[0]), "r"((a)[1]), "r"((a)[2]), "r"((a)[3]), \
          "r"(b0), "r"(b1))

// GEMM SMEM tile geometry: rows x 32 bf16 data, 80-byte row stride (pad 8)
#define ROWB 80
#define TILEA (128 * ROWB)        // 10240 (A: 128 rows)
#define TILEBB (256 * ROWB)       // 20480 (B: 256 rows)
#define STAGEB (2 * TILEA + 2 * TILEBB)  // 61440
#define NSTAGE 3
#define SMEM_BYTES (NSTAGE * STAGEB)     // 184320

__device__ __forceinline__ float gelu_f(float v) {
    return 0.5f * v * (1.f + erff(v * 0.70710678118654752f));
}
__device__ __forceinline__ void split_pair(float v, __nv_bfloat16& h, __nv_bfloat16& l) {
    h = __float2bfloat16(v);
    l = __float2bfloat16(v - __bfloat162float(h));
}

// ---------------- convert fp32 -> bf16 hi/lo pair --------------------------
__global__ void cvt_pair(const float* __restrict__ in, __nv_bfloat16* __restrict__ oh,
                         __nv_bfloat16* __restrict__ ol, int n4) {
    int i = blockIdx.x * blockDim.x + threadIdx.x;
    if (i >= n4) return;
    float4 v = ((const float4*)in)[i];
    __nv_bfloat162 h0, h1, l0, l1;
    split_pair(v.x, h0.x, l0.x);
    split_pair(v.y, h0.y, l0.y);
    split_pair(v.z, h1.x, l1.x);
    split_pair(v.w, h1.y, l1.y);
    ((__nv_bfloat162*)oh)[i * 2] = h0;
    ((__nv_bfloat162*)oh)[i * 2 + 1] = h1;
    ((__nv_bfloat162*)ol)[i * 2] = l0;
    ((__nv_bfloat162*)ol)[i * 2 + 1] = l1;
}

// ---------------- LayerNorm -> bf16 hi/lo pair -----------------------------
__global__ void ln_pair_kernel(const float* __restrict__ x, const float* __restrict__ w,
                               const float* __restrict__ b, __nv_bfloat16* __restrict__ oh,
                               __nv_bfloat16* __restrict__ ol) {
    int row = blockIdx.x;
    int tid = threadIdx.x;
    const float4* xr = (const float4*)(x + (size_t)row * DM);
    float4 v = xr[tid];
    float s = v.x + v.y + v.z + v.w;
    float s2 = v.x * v.x + v.y * v.y + v.z * v.z + v.w * v.w;
    __shared__ float red[16];
#pragma unroll
    for (int off = 16; off > 0; off >>= 1) {
        s += __shfl_xor_sync(0xffffffffu, s, off);
        s2 += __shfl_xor_sync(0xffffffffu, s2, off);
    }
    int wid = tid >> 5;
    if ((tid & 31) == 0) { red[wid] = s; red[8 + wid] = s2; }
    __syncthreads();
    if (tid < 32) {
        s = (tid < 8) ? red[tid] : 0.f;
        s2 = (tid < 8) ? red[8 + tid] : 0.f;
#pragma unroll
        for (int off = 4; off > 0; off >>= 1) {
            s += __shfl_xor_sync(0xffffffffu, s, off);
            s2 += __shfl_xor_sync(0xffffffffu, s2, off);
        }
        if (tid == 0) {
            float mu = s * (1.f / DM);
            float var = s2 * (1.f / DM) - mu * mu;
            red[0] = mu;
            red[1] = rsqrtf(var + 1e-5f);
        }
    }
    __syncthreads();
    float mu = red[0], rstd = red[1];
    float4 wv = ((const float4*)w)[tid];
    float4 bv = ((const float4*)b)[tid];
    float4 o;
    o.x = (v.x - mu) * rstd * wv.x + bv.x;
    o.y = (v.y - mu) * rstd * wv.y + bv.y;
    o.z = (v.z - mu) * rstd * wv.z + bv.z;
    o.w = (v.w - mu) * rstd * wv.w + bv.w;
    __nv_bfloat162 h0, h1, l0, l1;
    split_pair(o.x, h0.x, l0.x);
    split_pair(o.y, h0.y, l0.y);
    split_pair(o.z, h1.x, l1.x);
    split_pair(o.w, h1.y, l1.y);
    size_t base = (size_t)row * DM;
    ((__nv_bfloat162*)(oh + base))[tid * 2] = h0;
    ((__nv_bfloat162*)(oh + base))[tid * 2 + 1] = h1;
    ((__nv_bfloat162*)(ol + base))[tid * 2] = l0;
    ((__nv_bfloat162*)(ol + base))[tid * 2 + 1] = l1;
}

// ---------------- bf16x3 GEMM via mma.sync, 128x256 tile, 3-stage ----------
// (identical to the round-8 kernel that measured 2392us)
template <int EPI>
__global__ void __launch_bounds__(256, 1) gemm_bf16x3(
    const __nv_bfloat16* __restrict__ Ah, const __nv_bfloat16* __restrict__ Al,
    const __nv_bfloat16* __restrict__ Wh, const __nv_bfloat16* __restrict__ Wl,
    const float* __restrict__ bias, const float* __restrict__ res,
    float* __restrict__ Cf, __nv_bfloat16* __restrict__ Oh,
    __nv_bfloat16* __restrict__ Ol, int N, int K) {
    extern __shared__ char smem[];
    uint32_t sbase = s2u(smem);
    int tid = threadIdx.x;
    int w = tid >> 5, lane = tid & 31;
    int bm = blockIdx.y, bn = blockIdx.x;
    int mbase = (w & 1) * 64, nbase = (w >> 1) * 64;

    const __nv_bfloat16* srcA[2];
    const __nv_bfloat16* srcB[2];
    srcA[0] = Ah + (size_t)bm * 128 * K;
    srcA[1] = Al + (size_t)bm * 128 * K;
    srcB[0] = Wh + (size_t)bn * 256 * K;
    srcB[1] = Wl + (size_t)bn * 256 * K;

    int g = lane >> 3, lr = lane & 7;
    uint32_t offA = (uint32_t)((mbase + (g & 1) * 8 + lr) * ROWB + (g >> 1) * 16);
    uint32_t offB = (uint32_t)((nbase + (g >> 1) * 8 + lr) * ROWB + (g & 1) * 16);

    float acc[4][8][4];
#pragma unroll
    for (int mt = 0; mt < 4; mt++)
#pragma unroll
        for (int nt = 0; nt < 8; nt++)
#pragma unroll
            for (int u = 0; u < 4; u++) acc[mt][nt][u] = 0.f;

    int NK = K >> 5;  // BK = 32

#define LOAD_STAGE(s_, buf_)                                                   \
    do {                                                                       \
        uint32_t sb_ = sbase + (buf_) * STAGEB;                                \
        int k0_ = (s_) << 5;                                                   \
        _Pragma("unroll")                                                      \
        for (int t = 0; t < 2; t++) {                                          \
            _Pragma("unroll")                                                  \
            for (int u = 0; u < 2; u++) {                                      \
                int idx = tid + u * 256;                                       \
                int r = idx >> 2, c = idx & 3;                                 \
                cp_async16(sb_ + t * TILEA + r * ROWB + c * 16,                \
                           srcA[t] + (size_t)r * K + k0_ + c * 8);             \
            }                                                                  \
        }                                                                      \
        _Pragma("unroll")                                                      \
        for (int t = 0; t < 2; t++) {                                          \
            uint32_t db_ = sb_ + 2 * TILEA + t * TILEBB;                       \
            _Pragma("unroll")                                                  \
            for (int u = 0; u < 4; u++) {                                      \
                int idx = tid + u * 256;                                       \
                int r = idx >> 2, c = idx & 3;                                 \
                cp_async16(db_ + r * ROWB + c * 16,                            \
                           srcB[t] + (size_t)r * K + k0_ + c * 8);             \
            }                                                                  \
        }                                                                      \
    } while (0)

    LOAD_STAGE(0, 0);
    cp_commit();
    LOAD_STAGE(1, 1);
    cp_commit();

    int buf = 0;
    int buf2 = 2;
    for (int k = 0; k < NK; k++) {
        cp_wait<1>();
        __syncthreads();

        if (k + 2 < NK) LOAD_STAGE(k + 2, buf2);
        cp_commit();

        uint32_t sb = sbase + buf * STAGEB;
        uint32_t aAh = sb + offA, aAl = sb + TILEA + offA;
        uint32_t aBh = sb + 2 * TILEA + offB, aBl = sb + 2 * TILEA + TILEBB + offB;

#pragma unroll
        for (int ks = 0; ks < 2; ks++) {
            uint32_t ko = ks * 32;
            uint32_t ah[4][4], al[4][4];
#pragma unroll
            for (int mt = 0; mt < 4; mt++) {
                LDSM4(ah[mt], aAh + ko + mt * (16 * ROWB));
                LDSM4(al[mt], aAl + ko + mt * (16 * ROWB));
            }
#pragma unroll
            for (int p = 0; p < 4; p++) {
                uint32_t qh[4], ql[4];
                LDSM4(qh, aBh + ko + p * (16 * ROWB));
                LDSM4(ql, aBl + ko + p * (16 * ROWB));
#pragma unroll
                for (int mt = 0; mt < 4; mt++) {
                    MMA16816(acc[mt][2 * p], ah[mt], qh[0], qh[1]);
                    MMA16816(acc[mt][2 * p], ah[mt], ql[0], ql[1]);
                    MMA16816(acc[mt][2 * p], al[mt], qh[0], qh[1]);
                    MMA16816(acc[mt][2 * p + 1], ah[mt], qh[2], qh[3]);
                    MMA16816(acc[mt][2 * p + 1], ah[mt], ql[2], ql[3]);
                    MMA16816(acc[mt][2 * p + 1], al[mt], qh[2], qh[3]);
                }
            }
        }
        buf = (buf == 2) ? 0 : buf + 1;
        buf2 = (buf2 == 2) ? 0 : buf2 + 1;
    }
#undef LOAD_STAGE

    int l4 = lane >> 2, l2 = (lane & 3) * 2;
#pragma unroll
    for (int mt = 0; mt < 4; mt++) {
        int row = bm * 128 + mbase + mt * 16 + l4;
#pragma unroll
        for (int nt = 0; nt < 8; nt++) {
            int col = bn * 256 + nbase + nt * 8 + l2;
            float2 bv = *(const float2*)(bias + col);
            float v0 = acc[mt][nt][0] + bv.x;
            float v1 = acc[mt][nt][1] + bv.y;
            float v2 = acc[mt][nt][2] + bv.x;
            float v3 = acc[mt][nt][3] + bv.y;
            size_t p0 = (size_t)row * N + col;
            size_t p1 = (size_t)(row + 8) * N + col;
            if (EPI == 2) {
                float2 rv0 = *(const float2*)(res + p0);
                float2 rv1 = *(const float2*)(res + p1);
                v0 += rv0.x; v1 += rv0.y; v2 += rv1.x; v3 += rv1.y;
            }
            if (EPI == 1) {
                v0 = gelu_f(v0); v1 = gelu_f(v1);
                v2 = gelu_f(v2); v3 = gelu_f(v3);
                __nv_bfloat162 hp0, hp1, lp0, lp1;
                split_pair(v0, hp0.x, lp0.x);
                split_pair(v1, hp0.y, lp0.y);
                split_pair(v2, hp1.x, lp1.x);
                split_pair(v3, hp1.y, lp1.y);
                *(__nv_bfloat162*)(Oh + p0) = hp0;
                *(__nv_bfloat162*)(Oh + p1) = hp1;
                *(__nv_bfloat162*)(Ol + p0) = lp0;
                *(__nv_bfloat162*)(Ol + p1) = lp1;
            } else {
                *(float2*)(Cf + p0) = make_float2(v0, v1);
                *(float2*)(Cf + p1) = make_float2(v2, v3);
            }
        }
    }
}

// ---------------- HMMA flash attention --------------------------------------
// Per CTA: 128 q-rows x full 512 keys. 8 warps, each owns 16 q-rows.
// Q,K fp16 two-limb (3 MMA terms for S), P fp16, V fp16 two-limb (2 terms).
// Output written as bf16 hi/lo pair for the bf16x3 out-proj GEMM.
#define QT 128
#define ROWH 144  // bytes per SMEM row (72 halfs); 144%128=16 -> conflict-free ldsm
#define AQH 0
#define AQL (128 * ROWH)            // 18432
#define AKH (2 * 128 * ROWH)        // 36864
#define AKL (AKH + 64 * ROWH)       // 46080
#define AVH (AKL + 64 * ROWH)       // 55296
#define AVL (AVH + 64 * ROWH)       // 64512
#define ATTN_SMEM (AVL + 64 * ROWH) // 73728

__device__ __forceinline__ void h_split4(float4 v, uint32_t& h01, uint32_t& h23,
                                         uint32_t& l01, uint32_t& l23) {
    __half hx = __float2half_rn(v.x), hy = __float2half_rn(v.y);
    __half hz = __float2half_rn(v.z), hw = __float2half_rn(v.w);
    __half lx = __float2half_rn(v.x - __half2float(hx));
    __half ly = __float2half_rn(v.y - __half2float(hy));
    __half lz = __float2half_rn(v.z - __half2float(hz));
    __half lw = __float2half_rn(v.w - __half2float(hw));
    __half2 a = __halves2half2(hx, hy), b = __halves2half2(hz, hw);
    __half2 c = __halves2half2(lx, ly), d = __halves2half2(lz, lw);
    h01 = *(uint32_t*)&a; h23 = *(uint32_t*)&b;
    l01 = *(uint32_t*)&c; l23 = *(uint32_t*)&d;
}

__global__ void __launch_bounds__(256, 1) attn_hmma(
    const float* __restrict__ qkv, const float* __restrict__ rel_bias,
    __nv_bfloat16* __restrict__ oh, __nv_bfloat16* __restrict__ ol) {
    extern __shared__ char smem[];
    uint32_t sb = s2u(smem);
    int tid = threadIdx.x, w = tid >> 5, lane = tid & 31;
    int qt = blockIdx.x, h = blockIdx.y, b = blockIdx.z;

    const float* qbase = qkv + (size_t)(b * SEQ + qt * QT) * QKVD + h * HDIM;
    const float* kbase = qkv + (size_t)(b * SEQ) * QKVD + DM + h * HDIM;
    const float* vbase = kbase + DM;
    const float* biasrow = rel_bias + h * (2 * SEQ - 1);

    // ---- load Q tile: 128x64 fp32 -> fp16 limb pair in SMEM ----
#pragma unroll
    for (int i = 0; i < 8; i++) {
        int j = tid + i * 256;
        int r = j >> 4, c4 = j & 15;
        float4 v = *(const float4*)(qbase + (size_t)r * QKVD + c4 * 4);
        uint32_t h01, h23, l01, l23;
        h_split4(v, h01, h23, l01, l23);
        char* dq = smem + r * ROWH + c4 * 8;
        *(uint32_t*)(dq + AQH) = h01;
        *(uint32_t*)(dq + AQH + 4) = h23;
        *(uint32_t*)(dq + AQL) = l01;
        *(uint32_t*)(dq + AQL + 4) = l23;
    }

    int g = lane >> 3, lr = lane & 7;
    uint32_t offQh = sb + AQH + (uint32_t)((w * 16 + (g & 1) * 8 + lr) * ROWH + (g >> 1) * 16);
    uint32_t offQl = offQh + (AQL - AQH);
    uint32_t offKh = sb + AKH + (uint32_t)(((g >> 1) * 8 + lr) * ROWH + (g & 1) * 16);
    uint32_t offKl = offKh + 64 * ROWH;
    uint32_t offVh = sb + AVH + (uint32_t)(((g & 1) * 8 + lr) * ROWH + (g >> 1) * 16);
    uint32_t offVl = offVh + 64 * ROWH;

    int qg0 = qt * QT + w * 16 + (lane >> 2);
    const float* brow = biasrow + qg0 + (SEQ - 1);

    float m0 = -1e30f, m1 = -1e30f, l0 = 0.f, l1 = 0.f;
    float oacc[8][4];
#pragma unroll
    for (int j = 0; j < 8; j++)
#pragma unroll
        for (int u = 0; u < 4; u++) oacc[j][u] = 0.f;

    // prefetch K/V tile 0 into registers
    float4 kreg[4], vreg[4];
#pragma unroll
    for (int i = 0; i < 4; i++) {
        int j = tid + i * 256;
        int r = j >> 4, c4 = j & 15;
        kreg[i] = *(const float4*)(kbase + (size_t)r * QKVD + c4 * 4);
        vreg[i] = *(const float4*)(vbase + (size_t)r * QKVD + c4 * 4);
    }

    for (int kt = 0; kt < 8; kt++) {
        __syncthreads();  // prior compute done; SMEM K/V writable (covers Q on kt=0)
        // store prefetched K/V (fp16 limbs)
#pragma unroll
        for (int i = 0; i < 4; i++) {
            int j = tid + i * 256;
            int r = j >> 4, c4 = j & 15;
            uint32_t h01, h23, l01, l23;
            h_split4(kreg[i], h01, h23, l01, l23);
            char* dk = smem + r * ROWH + c4 * 8;
            *(uint32_t*)(dk + AKH) = h01;
            *(uint32_t*)(dk + AKH + 4) = h23;
            *(uint32_t*)(dk + AKL) = l01;
            *(uint32_t*)(dk + AKL + 4) = l23;
            h_split4(vreg[i], h01, h23, l01, l23);
            *(uint32_t*)(dk + AVH) = h01;
            *(uint32_t*)(dk + AVH + 4) = h23;
            *(uint32_t*)(dk + AVL) = l01;
            *(uint32_t*)(dk + AVL + 4) = l23;
        }
        __syncthreads();
        if (kt < 7) {
#pragma unroll
            for (int i = 0; i < 4; i++) {
                int j = tid + i * 256;
                int r = j >> 4, c4 = j & 15;
                kreg[i] = *(const float4*)(kbase + (size_t)((kt + 1) * 64 + r) * QKVD + c4 * 4);
                vreg[i] = *(const float4*)(vbase + (size_t)((kt + 1) * 64 + r) * QKVD + c4 * 4);
            }
        }

        // ---- S = Q K^T (fp16x3) ----
        float sacc[8][4];
#pragma unroll
        for (int j = 0; j < 8; j++)
#pragma unroll
            for (int u = 0; u < 4; u++) sacc[j][u] = 0.f;
#pragma unroll
        for (int kk = 0; kk < 4; kk++) {
            uint32_t qh4[4], ql4[4];
            LDSM4(qh4, offQh + kk * 32);
            LDSM4(ql4, offQl + kk * 32);
#pragma unroll
            for (int kb = 0; kb < 4; kb++) {
                uint32_t kh4[4], kl4[4];
                LDSM4(kh4, offKh + kb * (16 * ROWH) + kk * 32);
                LDSM4(kl4, offKl + kb * (16 * ROWH) + kk * 32);
                MMAF16(sacc[2 * kb], qh4, kh4[0], kh4[1]);
                MMAF16(sacc[2 * kb], qh4, kl4[0], kl4[1]);
                MMAF16(sacc[2 * kb], ql4, kh4[0], kh4[1]);
                MMAF16(sacc[2 * kb + 1], qh4, kh4[2], kh4[3]);
                MMAF16(sacc[2 * kb + 1], qh4, kl4[2], kl4[3]);
                MMAF16(sacc[2 * kb + 1], ql4, kh4[2], kh4[3]);
            }
        }

        // ---- scale + rel-pos bias + online softmax ----
        int kgb = kt * 64 + (lane & 3) * 2;
        float mn0 = m0, mn1 = m1;
#pragma unroll
        for (int j = 0; j < 8; j++) {
            int kg = kgb + 8 * j;
            sacc[j][0] = sacc[j][0] * 0.125f + __ldg(brow - kg);
            sacc[j][1] = sacc[j][1] * 0.125f + __ldg(brow - kg - 1);
            sacc[j][2] = sacc[j][2] * 0.125f + __ldg(brow - kg + 8);
            sacc[j][3] = sacc[j][3] * 0.125f + __ldg(brow - kg + 7);
            mn0 = fmaxf(mn0, fmaxf(sacc[j][0], sacc[j][1]));
            mn1 = fmaxf(mn1, fmaxf(sacc[j][2], sacc[j][3]));
        }
        mn0 = fmaxf(mn0, __shfl_xor_sync(0xffffffffu, mn0, 1));
        mn0 = fmaxf(mn0, __shfl_xor_sync(0xffffffffu, mn0, 2));
        mn1 = fmaxf(mn1, __shfl_xor_sync(0xffffffffu, mn1, 1));
        mn1 = fmaxf(mn1, __shfl_xor_sync(0xffffffffu, mn1, 2));
        float fac0 = __expf(m0 - mn0), fac1 = __expf(m1 - mn1);
        m0 = mn0; m1 = mn1;

        float rs0 = 0.f, rs1 = 0.f;
        uint32_t pf[16];
#pragma unroll
        for (int j = 0; j < 8; j++) {
            float p0 = __expf(sacc[j][0] - m0), p1 = __expf(sacc[j][1] - m0);
            float p2 = __expf(sacc[j][2] - m1), p3 = __expf(sacc[j][3] - m1);
            rs0 += p0 + p1;
            rs1 += p2 + p3;
            __half2 hp0 = __floats2half2_rn(p0, p1);
            __half2 hp1 = __floats2half2_rn(p2, p3);
            pf[2 * j] = *(uint32_t*)&hp0;
            pf[2 * j + 1] = *(uint32_t*)&hp1;
        }
        rs0 += __shfl_xor_sync(0xffffffffu, rs0, 1);
        rs0 += __shfl_xor_sync(0xffffffffu, rs0, 2);
        rs1 += __shfl_xor_sync(0xffffffffu, rs1, 1);
        rs1 += __shfl_xor_sync(0xffffffffu, rs1, 2);
        l0 = l0 * fac0 + rs0;
        l1 = l1 * fac1 + rs1;
#pragma unroll
        for (int j = 0; j < 8; j++) {
            oacc[j][0] *= fac0; oacc[j][1] *= fac0;
            oacc[j][2] *= fac1; oacc[j][3] *= fac1;
        }

        // ---- O += P V (P fp16, V fp16x2; V^T via ldmatrix.trans) ----
#pragma unroll
        for (int kk = 0; kk < 4; kk++) {
            uint32_t ap[4] = {pf[4 * kk], pf[4 * kk + 1], pf[4 * kk + 2], pf[4 * kk + 3]};
#pragma unroll
            for (int hb = 0; hb < 4; hb++) {
                uint32_t vh4[4], vl4[4];
                LDSM4T(vh4, offVh + kk * (16 * ROWH) + hb * 32);
                LDSM4T(vl4, offVl + kk * (16 * ROWH) + hb * 32);
                MMAF16(oacc[2 * hb], ap, vh4[0], vh4[1]);
                MMAF16(oacc[2 * hb], ap, vl4[0], vl4[1]);
                MMAF16(oacc[2 * hb + 1], ap, vh4[2], vh4[3]);
                MMAF16(oacc[2 * hb + 1], ap, vl4[2], vl4[3]);
            }
        }
    }

    // ---- epilogue: O/l -> bf16 hi/lo pairs ----
    float i0 = 1.f / l0, i1 = 1.f / l1;
    size_t row0 = (size_t)(b * SEQ + qt * QT + w * 16 + (lane >> 2));
    size_t base0 = row0 * DM + h * HDIM + (lane & 3) * 2;
#pragma unroll
    for (int j = 0; j < 8; j++) {
        float v0 = oacc[j][0] * i0, v1 = oacc[j][1] * i0;
        float v2 = oacc[j][2] * i1, v3 = oacc[j][3] * i1;
        __nv_bfloat162 hp0, hp1, lp0, lp1;
        split_pair(v0, hp0.x, lp0.x);
        split_pair(v1, hp0.y, lp0.y);
        split_pair(v2, hp1.x, lp1.x);
        split_pair(v3, hp1.y, lp1.y);
        *(__nv_bfloat162*)(oh + base0 + 8 * j) = hp0;
        *(__nv_bfloat162*)(ol + base0 + 8 * j) = lp0;
        *(__nv_bfloat162*)(oh + base0 + 8 * (size_t)DM + 8 * j) = hp1;
        *(__nv_bfloat162*)(ol + base0 + 8 * (size_t)DM + 8 * j) = lp1;
    }
}

// ---------------- launch ---------------------------------------------------
extern "C" void kernel_launch(void* const* d_in, const int* in_sizes, int n_in,
                              void* d_out, int out_size) {
    const float* x = (const float*)d_in[0];
    const float* in_w = (const float*)d_in[1];
    const float* in_b = (const float*)d_in[2];
    const float* out_w = (const float*)d_in[3];
    const float* out_b = (const float*)d_in[4];
    const float* rel_bias = (const float*)d_in[5];
    const float* w1 = (const float*)d_in[6];
    const float* b1 = (const float*)d_in[7];
    const float* w2 = (const float*)d_in[8];
    const float* b2 = (const float*)d_in[9];
    const float* ln1w = (const float*)d_in[10];
    const float* ln1b = (const float*)d_in[11];
    const float* ln2w = (const float*)d_in[12];
    const float* ln2b = (const float*)d_in[13];
    float* out = (float*)d_out;

    __nv_bfloat16 *wh, *wl, *xh, *xl, *ah, *al;
    float* qkv;
    cudaGetSymbolAddress((void**)&wh, g_wh);
    cudaGetSymbolAddress((void**)&wl, g_wl);
    cudaGetSymbolAddress((void**)&xh, g_xh);
    cudaGetSymbolAddress((void**)&xl, g_xl);
    cudaGetSymbolAddress((void**)&ah, g_ah);
    cudaGetSymbolAddress((void**)&al, g_al);
    cudaGetSymbolAddress((void**)&qkv, g_qkv);

    cudaFuncSetAttribute(gemm_bf16x3<0>, cudaFuncAttributeMaxDynamicSharedMemorySize, SMEM_BYTES);
    cudaFuncSetAttribute(gemm_bf16x3<1>, cudaFuncAttributeMaxDynamicSharedMemorySize, SMEM_BYTES);
    cudaFuncSetAttribute(gemm_bf16x3<2>, cudaFuncAttributeMaxDynamicSharedMemorySize, SMEM_BYTES);
    cudaFuncSetAttribute(attn_hmma, cudaFuncAttributeMaxDynamicSharedMemorySize, ATTN_SMEM);

    const size_t OFF_INW = 0;
    const size_t OFF_OUTW = 3145728;
    const size_t OFF_W1 = 4194304;
    const size_t OFF_W2 = 8388608;

    cvt_pair<<<(3145728 / 4 + 255) / 256, 256>>>(in_w, wh + OFF_INW, wl + OFF_INW, 3145728 / 4);
    cvt_pair<<<(1048576 / 4 + 255) / 256, 256>>>(out_w, wh + OFF_OUTW, wl + OFF_OUTW, 1048576 / 4);
    cvt_pair<<<(4194304 / 4 + 255) / 256, 256>>>(w1, wh + OFF_W1, wl + OFF_W1, 4194304 / 4);
    cvt_pair<<<(4194304 / 4 + 255) / 256, 256>>>(w2, wh + OFF_W2, wl + OFF_W2, 4194304 / 4);

    // 1. xn = LN1(x) -> bf16 pair
    ln_pair_kernel<<<MROWS, 256>>>(x, ln1w, ln1b, xh, xl);
    // 2. qkv = xn @ in_proj_w^T + b
    gemm_bf16x3<0><<<dim3(QKVD / 256, MROWS / 128), 256, SMEM_BYTES>>>(
        xh, xl, wh + OFF_INW, wl + OFF_INW, in_b, nullptr, qkv, nullptr, nullptr,
        QKVD, DM);
    // 3. attention (HMMA flash) -> bf16 pair
    attn_hmma<<<dim3(SEQ / QT, NH, BSZ), 256, ATTN_SMEM>>>(qkv, rel_bias, xh, xl);
    // 4. out = x + attn @ out_w^T + b
    gemm_bf16x3<2><<<dim3(DM / 256, MROWS / 128), 256, SMEM_BYTES>>>(
        xh, xl, wh + OFF_OUTW, wl + OFF_OUTW, out_b, x, out, nullptr, nullptr,
        DM, DM);
    // 5. xn = LN2(out) -> bf16 pair
    ln_pair_kernel<<<MROWS, 256>>>(out, ln2w, ln2b, xh, xl);
    // 6. ffn = gelu(xn @ w1^T + b1) -> bf16 pair
    gemm_bf16x3<1><<<dim3(DFF / 256, MROWS / 128), 256, SMEM_BYTES>>>(
        xh, xl, wh + OFF_W1, wl + OFF_W1, b1, nullptr, nullptr, ah, al,
        DFF, DM);
    // 7. out = out + ffn @ w2^T + b2
    gemm_bf16x3<2><<<dim3(DM / 256, MROWS / 128), 256, SMEM_BYTES>>>(
        ah, al, wh + OFF_W2, wl + OFF_W2, b2, out, out, nullptr, nullptr,
        DM, DFF);
}

// round 17
// speedup vs baseline: 5.4416x; 2.0497x over previous
#include <cuda_runtime.h>
#include <cuda_fp16.h>
#include <math.h>
#include <stdint.h>

#define BSZ 16
#define SEQ 512
#define DM 1024
#define NH 16
#define HDIM 64
#define DFF 4096
#define MROWS (BSZ * SEQ)  // 8192
#define QKVD (3 * DM)      // 3072

// ---------------- scratch (device globals; no cudaMalloc allowed) ----------
__device__ __align__(16) __half g_w[12582912];               // all 4 weight mats
__device__ __align__(16) __half g_x[(size_t)MROWS * DM];     // activations
__device__ __align__(16) __half g_a[(size_t)MROWS * DFF];    // ffn activations
__device__ float g_qkv[(size_t)MROWS * QKVD];

// ---------------- PTX helpers ----------------------------------------------
__device__ __forceinline__ uint32_t s2u(const void* p) {
    uint32_t a;
    asm("{ .reg .u64 t; cvta.to.shared.u64 t, %1; cvt.u32.u64 %0, t; }"
        : "=r"(a) : "l"(p));
    return a;
}
__device__ __forceinline__ void cp_async16(uint32_t dst, const void* src) {
    asm volatile("cp.async.cg.shared.global [%0], [%1], 16;"
                 :: "r"(dst), "l"(src) : "memory");
}
__device__ __forceinline__ void cp_commit() {
    asm volatile("cp.async.commit_group;" ::: "memory");
}
template <int N>
__device__ __forceinline__ void cp_wait() {
    asm volatile("cp.async.wait_group %0;" :: "n"(N) : "memory");
}
#define LDSM4(d, a) \
    asm volatile("ldmatrix.sync.aligned.m8n8.x4.shared.b16 {%0,%1,%2,%3}, [%4];" \
                 : "=r"((d)[0]), "=r"((d)[1]), "=r"((d)[2]), "=r"((d)[3]) : "r"(a))
#define LDSM4T(d, a) \
    asm volatile("ldmatrix.sync.aligned.m8n8.x4.trans.shared.b16 {%0,%1,%2,%3}, [%4];" \
                 : "=r"((d)[0]), "=r"((d)[1]), "=r"((d)[2]), "=r"((d)[3]) : "r"(a))
#define MMAF16(c, a, b0, b1) \
    asm volatile( \
        "mma.sync.aligned.m16n8k16.row.col.f32.f16.f16.f32 " \
        "{%0,%1,%2,%3},{%4,%5,%6,%7},{%8,%9},{%0,%1,%2,%3};" \
        : "+f"((c)[0]), "+f"((c)[1]), "+f"((c)[2]), "+f"((c)[3]) \
        : "r"((a)[0]), "r"((a)[1]), "r"((a)[2]), "r"((a)[3]), \
          "r"(b0), "r"(b1))

// GEMM SMEM tile geometry: rows x 32 fp16 data, 80-byte row stride (pad 16B)
#define ROWB 80
#define TILEA (128 * ROWB)               // 10240 (A: 128 rows)
#define TILEBB (256 * ROWB)              // 20480 (B: 256 rows)
#define STAGEB (TILEA + TILEBB)          // 30720
#define SMEM_BYTES (3 * STAGEB)          // 92160

__device__ __forceinline__ float gelu_f(float v) {
    return 0.5f * v * (1.f + erff(v * 0.70710678118654752f));
}

// ---------------- convert fp32 -> fp16 --------------------------------------
__global__ void cvt_f16(const float* __restrict__ in, __half* __restrict__ o, int n4) {
    int i = blockIdx.x * blockDim.x + threadIdx.x;
    if (i >= n4) return;
    float4 v = ((const float4*)in)[i];
    __half2 a = __floats2half2_rn(v.x, v.y);
    __half2 b = __floats2half2_rn(v.z, v.w);
    ((__half2*)o)[i * 2] = a;
    ((__half2*)o)[i * 2 + 1] = b;
}

// ---------------- LayerNorm -> fp16 -----------------------------------------
__global__ void ln_f16(const float* __restrict__ x, const float* __restrict__ w,
                       const float* __restrict__ b, __half* __restrict__ o16) {
    int row = blockIdx.x;
    int tid = threadIdx.x;
    const float4* xr = (const float4*)(x + (size_t)row * DM);
    float4 v = xr[tid];
    float s = v.x + v.y + v.z + v.w;
    float s2 = v.x * v.x + v.y * v.y + v.z * v.z + v.w * v.w;
    __shared__ float red[16];
#pragma unroll
    for (int off = 16; off > 0; off >>= 1) {
        s += __shfl_xor_sync(0xffffffffu, s, off);
        s2 += __shfl_xor_sync(0xffffffffu, s2, off);
    }
    int wid = tid >> 5;
    if ((tid & 31) == 0) { red[wid] = s; red[8 + wid] = s2; }
    __syncthreads();
    if (tid < 32) {
        s = (tid < 8) ? red[tid] : 0.f;
        s2 = (tid < 8) ? red[8 + tid] : 0.f;
#pragma unroll
        for (int off = 4; off > 0; off >>= 1) {
            s += __shfl_xor_sync(0xffffffffu, s, off);
            s2 += __shfl_xor_sync(0xffffffffu, s2, off);
        }
        if (tid == 0) {
            float mu = s * (1.f / DM);
            float var = s2 * (1.f / DM) - mu * mu;
            red[0] = mu;
            red[1] = rsqrtf(var + 1e-5f);
        }
    }
    __syncthreads();
    float mu = red[0], rstd = red[1];
    float4 wv = ((const float4*)w)[tid];
    float4 bv = ((const float4*)b)[tid];
    float o0 = (v.x - mu) * rstd * wv.x + bv.x;
    float o1 = (v.y - mu) * rstd * wv.y + bv.y;
    float o2 = (v.z - mu) * rstd * wv.z + bv.z;
    float o3 = (v.w - mu) * rstd * wv.w + bv.w;
    size_t base = (size_t)row * DM;
    ((__half2*)(o16 + base))[tid * 2] = __floats2half2_rn(o0, o1);
    ((__half2*)(o16 + base))[tid * 2 + 1] = __floats2half2_rn(o2, o3);
}

// ---------------- fp16 GEMM via mma.sync, 128x256 tile, 3-stage ------------
// C[M,N] = A * W^T (+bias, EPI). A,W fp16 single (K-major).
// CTA tile 128x256, BK=32, 256 thr, warp tile 64x64 (2m x 4n warps).
// EPI: 0 = bias -> Cf; 1 = gelu(bias+acc) -> O16 (fp16); 2 = res+bias+acc -> Cf
template <int EPI>
__global__ void __launch_bounds__(256, 1) gemm_f16(
    const __half* __restrict__ A, const __half* __restrict__ W,
    const float* __restrict__ bias, const float* __restrict__ res,
    float* __restrict__ Cf, __half* __restrict__ O16, int N, int K) {
    extern __shared__ char smem[];
    uint32_t sbase = s2u(smem);
    int tid = threadIdx.x;
    int w = tid >> 5, lane = tid & 31;
    int bm = blockIdx.y, bn = blockIdx.x;
    int mbase = (w & 1) * 64, nbase = (w >> 1) * 64;

    const __half* srcA = A + (size_t)bm * 128 * K;
    const __half* srcB = W + (size_t)bn * 256 * K;

    int g = lane >> 3, lr = lane & 7;
    uint32_t offA = (uint32_t)((mbase + (g & 1) * 8 + lr) * ROWB + (g >> 1) * 16);
    uint32_t offB = (uint32_t)((nbase + (g >> 1) * 8 + lr) * ROWB + (g & 1) * 16);

    float acc[4][8][4];
#pragma unroll
    for (int mt = 0; mt < 4; mt++)
#pragma unroll
        for (int nt = 0; nt < 8; nt++)
#pragma unroll
            for (int u = 0; u < 4; u++) acc[mt][nt][u] = 0.f;

    int NK = K >> 5;  // BK = 32

#define LOAD_STAGE(s_, buf_)                                                   \
    do {                                                                       \
        uint32_t sb_ = sbase + (buf_) * STAGEB;                                \
        int k0_ = (s_) << 5;                                                   \
        _Pragma("unroll")                                                      \
        for (int u = 0; u < 2; u++) {                                          \
            int idx = tid + u * 256;                                           \
            int r = idx >> 2, c = idx & 3;                                     \
            cp_async16(sb_ + r * ROWB + c * 16,                                \
                       srcA + (size_t)r * K + k0_ + c * 8);                    \
        }                                                                      \
        _Pragma("unroll")                                                      \
        for (int u = 0; u < 4; u++) {                                          \
            int idx = tid + u * 256;                                           \
            int r = idx >> 2, c = idx & 3;                                     \
            cp_async16(sb_ + TILEA + r * ROWB + c * 16,                        \
                       srcB + (size_t)r * K + k0_ + c * 8);                    \
        }                                                                      \
    } while (0)

    LOAD_STAGE(0, 0);
    cp_commit();
    LOAD_STAGE(1, 1);
    cp_commit();

    int buf = 0;
    int buf2 = 2;
    for (int k = 0; k < NK; k++) {
        cp_wait<1>();
        __syncthreads();

        if (k + 2 < NK) LOAD_STAGE(k + 2, buf2);
        cp_commit();

        uint32_t sb = sbase + buf * STAGEB;
        uint32_t aA = sb + offA;
        uint32_t aB = sb + TILEA + offB;

#pragma unroll
        for (int ks = 0; ks < 2; ks++) {
            uint32_t ko = ks * 32;
            uint32_t ah[4][4];
#pragma unroll
            for (int mt = 0; mt < 4; mt++)
                LDSM4(ah[mt], aA + ko + mt * (16 * ROWB));
#pragma unroll
            for (int p = 0; p < 4; p++) {
                uint32_t qh[4];
                LDSM4(qh, aB + ko + p * (16 * ROWB));
#pragma unroll
                for (int mt = 0; mt < 4; mt++) {
                    MMAF16(acc[mt][2 * p], ah[mt], qh[0], qh[1]);
                    MMAF16(acc[mt][2 * p + 1], ah[mt], qh[2], qh[3]);
                }
            }
        }
        buf = (buf == 2) ? 0 : buf + 1;
        buf2 = (buf2 == 2) ? 0 : buf2 + 1;
    }
#undef LOAD_STAGE

    // ---------------- epilogue (registers only) ----------------
    int l4 = lane >> 2, l2 = (lane & 3) * 2;
#pragma unroll
    for (int mt = 0; mt < 4; mt++) {
        int row = bm * 128 + mbase + mt * 16 + l4;
#pragma unroll
        for (int nt = 0; nt < 8; nt++) {
            int col = bn * 256 + nbase + nt * 8 + l2;
            float2 bv = *(const float2*)(bias + col);
            float v0 = acc[mt][nt][0] + bv.x;
            float v1 = acc[mt][nt][1] + bv.y;
            float v2 = acc[mt][nt][2] + bv.x;
            float v3 = acc[mt][nt][3] + bv.y;
            size_t p0 = (size_t)row * N + col;
            size_t p1 = (size_t)(row + 8) * N + col;
            if (EPI == 2) {
                float2 rv0 = *(const float2*)(res + p0);
                float2 rv1 = *(const float2*)(res + p1);
                v0 += rv0.x; v1 += rv0.y; v2 += rv1.x; v3 += rv1.y;
            }
            if (EPI == 1) {
                v0 = gelu_f(v0); v1 = gelu_f(v1);
                v2 = gelu_f(v2); v3 = gelu_f(v3);
                *(__half2*)(O16 + p0) = __floats2half2_rn(v0, v1);
                *(__half2*)(O16 + p1) = __floats2half2_rn(v2, v3);
            } else {
                *(float2*)(Cf + p0) = make_float2(v0, v1);
                *(float2*)(Cf + p1) = make_float2(v2, v3);
            }
        }
    }
}

// ---------------- HMMA flash attention --------------------------------------
// Per CTA: 128 q-rows x full 512 keys. 8 warps, each owns 16 q-rows.
// Q,K fp16 two-limb (3 MMA terms for S), P fp16, V fp16 two-limb (2 terms).
// Output written as fp16 single for the fp16 out-proj GEMM.
#define QT 128
#define ROWH 144  // bytes per SMEM row (72 halfs); conflict-free ldsm
#define AQH 0
#define AQL (128 * ROWH)            // 18432
#define AKH (2 * 128 * ROWH)        // 36864
#define AKL (AKH + 64 * ROWH)       // 46080
#define AVH (AKL + 64 * ROWH)       // 55296
#define AVL (AVH + 64 * ROWH)       // 64512
#define ATTN_SMEM (AVL + 64 * ROWH) // 73728

__device__ __forceinline__ void h_split4(float4 v, uint32_t& h01, uint32_t& h23,
                                         uint32_t& l01, uint32_t& l23) {
    __half hx = __float2half_rn(v.x), hy = __float2half_rn(v.y);
    __half hz = __float2half_rn(v.z), hw = __float2half_rn(v.w);
    __half lx = __float2half_rn(v.x - __half2float(hx));
    __half ly = __float2half_rn(v.y - __half2float(hy));
    __half lz = __float2half_rn(v.z - __half2float(hz));
    __half lw = __float2half_rn(v.w - __half2float(hw));
    __half2 a = __halves2half2(hx, hy), b = __halves2half2(hz, hw);
    __half2 c = __halves2half2(lx, ly), d = __halves2half2(lz, lw);
    h01 = *(uint32_t*)&a; h23 = *(uint32_t*)&b;
    l01 = *(uint32_t*)&c; l23 = *(uint32_t*)&d;
}

__global__ void __launch_bounds__(256, 1) attn_hmma(
    const float* __restrict__ qkv, const float* __restrict__ rel_bias,
    __half* __restrict__ o16) {
    extern __shared__ char smem[];
    uint32_t sb = s2u(smem);
    int tid = threadIdx.x, w = tid >> 5, lane = tid & 31;
    int qt = blockIdx.x, h = blockIdx.y, b = blockIdx.z;

    const float* qbase = qkv + (size_t)(b * SEQ + qt * QT) * QKVD + h * HDIM;
    const float* kbase = qkv + (size_t)(b * SEQ) * QKVD + DM + h * HDIM;
    const float* vbase = kbase + DM;
    const float* biasrow = rel_bias + h * (2 * SEQ - 1);

#pragma unroll
    for (int i = 0; i < 8; i++) {
        int j = tid + i * 256;
        int r = j >> 4, c4 = j & 15;
        float4 v = *(const float4*)(qbase + (size_t)r * QKVD + c4 * 4);
        uint32_t h01, h23, l01, l23;
        h_split4(v, h01, h23, l01, l23);
        char* dq = smem + r * ROWH + c4 * 8;
        *(uint32_t*)(dq + AQH) = h01;
        *(uint32_t*)(dq + AQH + 4) = h23;
        *(uint32_t*)(dq + AQL) = l01;
        *(uint32_t*)(dq + AQL + 4) = l23;
    }

    int g = lane >> 3, lr = lane & 7;
    uint32_t offQh = sb + AQH + (uint32_t)((w * 16 + (g & 1) * 8 + lr) * ROWH + (g >> 1) * 16);
    uint32_t offQl = offQh + (AQL - AQH);
    uint32_t offKh = sb + AKH + (uint32_t)(((g >> 1) * 8 + lr) * ROWH + (g & 1) * 16);
    uint32_t offKl = offKh + 64 * ROWH;
    uint32_t offVh = sb + AVH + (uint32_t)(((g & 1) * 8 + lr) * ROWH + (g >> 1) * 16);
    uint32_t offVl = offVh + 64 * ROWH;

    int qg0 = qt * QT + w * 16 + (lane >> 2);
    const float* brow = biasrow + qg0 + (SEQ - 1);

    float m0 = -1e30f, m1 = -1e30f, l0 = 0.f, l1 = 0.f;
    float oacc[8][4];
#pragma unroll
    for (int j = 0; j < 8; j++)
#pragma unroll
        for (int u = 0; u < 4; u++) oacc[j][u] = 0.f;

    float4 kreg[4], vreg[4];
#pragma unroll
    for (int i = 0; i < 4; i++) {
        int j = tid + i * 256;
        int r = j >> 4, c4 = j & 15;
        kreg[i] = *(const float4*)(kbase + (size_t)r * QKVD + c4 * 4);
        vreg[i] = *(const float4*)(vbase + (size_t)r * QKVD + c4 * 4);
    }

    for (int kt = 0; kt < 8; kt++) {
        __syncthreads();
#pragma unroll
        for (int i = 0; i < 4; i++) {
            int j = tid + i * 256;
            int r = j >> 4, c4 = j & 15;
            uint32_t h01, h23, l01, l23;
            h_split4(kreg[i], h01, h23, l01, l23);
            char* dk = smem + r * ROWH + c4 * 8;
            *(uint32_t*)(dk + AKH) = h01;
            *(uint32_t*)(dk + AKH + 4) = h23;
            *(uint32_t*)(dk + AKL) = l01;
            *(uint32_t*)(dk + AKL + 4) = l23;
            h_split4(vreg[i], h01, h23, l01, l23);
            *(uint32_t*)(dk + AVH) = h01;
            *(uint32_t*)(dk + AVH + 4) = h23;
            *(uint32_t*)(dk + AVL) = l01;
            *(uint32_t*)(dk + AVL + 4) = l23;
        }
        __syncthreads();
        if (kt < 7) {
#pragma unroll
            for (int i = 0; i < 4; i++) {
                int j = tid + i * 256;
                int r = j >> 4, c4 = j & 15;
                kreg[i] = *(const float4*)(kbase + (size_t)((kt + 1) * 64 + r) * QKVD + c4 * 4);
                vreg[i] = *(const float4*)(vbase + (size_t)((kt + 1) * 64 + r) * QKVD + c4 * 4);
            }
        }

        float sacc[8][4];
#pragma unroll
        for (int j = 0; j < 8; j++)
#pragma unroll
            for (int u = 0; u < 4; u++) sacc[j][u] = 0.f;
#pragma unroll
        for (int kk = 0; kk < 4; kk++) {
            uint32_t qh4[4], ql4[4];
            LDSM4(qh4, offQh + kk * 32);
            LDSM4(ql4, offQl + kk * 32);
#pragma unroll
            for (int kb = 0; kb < 4; kb++) {
                uint32_t kh4[4], kl4[4];
                LDSM4(kh4, offKh + kb * (16 * ROWH) + kk * 32);
                LDSM4(kl4, offKl + kb * (16 * ROWH) + kk * 32);
                MMAF16(sacc[2 * kb], qh4, kh4[0], kh4[1]);
                MMAF16(sacc[2 * kb], qh4, kl4[0], kl4[1]);
                MMAF16(sacc[2 * kb], ql4, kh4[0], kh4[1]);
                MMAF16(sacc[2 * kb + 1], qh4, kh4[2], kh4[3]);
                MMAF16(sacc[2 * kb + 1], qh4, kl4[2], kl4[3]);
                MMAF16(sacc[2 * kb + 1], ql4, kh4[2], kh4[3]);
            }
        }

        int kgb = kt * 64 + (lane & 3) * 2;
        float mn0 = m0, mn1 = m1;
#pragma unroll
        for (int j = 0; j < 8; j++) {
            int kg = kgb + 8 * j;
            sacc[j][0] = sacc[j][0] * 0.125f + __ldg(brow - kg);
            sacc[j][1] = sacc[j][1] * 0.125f + __ldg(brow - kg - 1);
            sacc[j][2] = sacc[j][2] * 0.125f + __ldg(brow - kg + 8);
            sacc[j][3] = sacc[j][3] * 0.125f + __ldg(brow - kg + 7);
            mn0 = fmaxf(mn0, fmaxf(sacc[j][0], sacc[j][1]));
            mn1 = fmaxf(mn1, fmaxf(sacc[j][2], sacc[j][3]));
        }
        mn0 = fmaxf(mn0, __shfl_xor_sync(0xffffffffu, mn0, 1));
        mn0 = fmaxf(mn0, __shfl_xor_sync(0xffffffffu, mn0, 2));
        mn1 = fmaxf(mn1, __shfl_xor_sync(0xffffffffu, mn1, 1));
        mn1 = fmaxf(mn1, __shfl_xor_sync(0xffffffffu, mn1, 2));
        float fac0 = __expf(m0 - mn0), fac1 = __expf(m1 - mn1);
        m0 = mn0; m1 = mn1;

        float rs0 = 0.f, rs1 = 0.f;
        uint32_t pf[16];
#pragma unroll
        for (int j = 0; j < 8; j++) {
            float p0 = __expf(sacc[j][0] - m0), p1 = __expf(sacc[j][1] - m0);
            float p2 = __expf(sacc[j][2] - m1), p3 = __expf(sacc[j][3] - m1);
            rs0 += p0 + p1;
            rs1 += p2 + p3;
            __half2 hp0 = __floats2half2_rn(p0, p1);
            __half2 hp1 = __floats2half2_rn(p2, p3);
            pf[2 * j] = *(uint32_t*)&hp0;
            pf[2 * j + 1] = *(uint32_t*)&hp1;
        }
        rs0 += __shfl_xor_sync(0xffffffffu, rs0, 1);
        rs0 += __shfl_xor_sync(0xffffffffu, rs0, 2);
        rs1 += __shfl_xor_sync(0xffffffffu, rs1, 1);
        rs1 += __shfl_xor_sync(0xffffffffu, rs1, 2);
        l0 = l0 * fac0 + rs0;
        l1 = l1 * fac1 + rs1;
#pragma unroll
        for (int j = 0; j < 8; j++) {
            oacc[j][0] *= fac0; oacc[j][1] *= fac0;
            oacc[j][2] *= fac1; oacc[j][3] *= fac1;
        }

#pragma unroll
        for (int kk = 0; kk < 4; kk++) {
            uint32_t ap[4] = {pf[4 * kk], pf[4 * kk + 1], pf[4 * kk + 2], pf[4 * kk + 3]};
#pragma unroll
            for (int hb = 0; hb < 4; hb++) {
                uint32_t vh4[4], vl4[4];
                LDSM4T(vh4, offVh + kk * (16 * ROWH) + hb * 32);
                LDSM4T(vl4, offVl + kk * (16 * ROWH) + hb * 32);
                MMAF16(oacc[2 * hb], ap, vh4[0], vh4[1]);
                MMAF16(oacc[2 * hb], ap, vl4[0], vl4[1]);
                MMAF16(oacc[2 * hb + 1], ap, vh4[2], vh4[3]);
                MMAF16(oacc[2 * hb + 1], ap, vl4[2], vl4[3]);
            }
        }
    }

    // ---- epilogue: O/l -> fp16 single ----
    float i0 = 1.f / l0, i1 = 1.f / l1;
    size_t row0 = (size_t)(b * SEQ + qt * QT + w * 16 + (lane >> 2));
    size_t base0 = row0 * DM + h * HDIM + (lane & 3) * 2;
#pragma unroll
    for (int j = 0; j < 8; j++) {
        *(__half2*)(o16 + base0 + 8 * j) =
            __floats2half2_rn(oacc[j][0] * i0, oacc[j][1] * i0);
        *(__half2*)(o16 + base0 + 8 * (size_t)DM + 8 * j) =
            __floats2half2_rn(oacc[j][2] * i1, oacc[j][3] * i1);
    }
}

// ---------------- launch ---------------------------------------------------
extern "C" void kernel_launch(void* const* d_in, const int* in_sizes, int n_in,
                              void* d_out, int out_size) {
    const float* x = (const float*)d_in[0];
    const float* in_w = (const float*)d_in[1];
    const float* in_b = (const float*)d_in[2];
    const float* out_w = (const float*)d_in[3];
    const float* out_b = (const float*)d_in[4];
    const float* rel_bias = (const float*)d_in[5];
    const float* w1 = (const float*)d_in[6];
    const float* b1 = (const float*)d_in[7];
    const float* w2 = (const float*)d_in[8];
    const float* b2 = (const float*)d_in[9];
    const float* ln1w = (const float*)d_in[10];
    const float* ln1b = (const float*)d_in[11];
    const float* ln2w = (const float*)d_in[12];
    const float* ln2b = (const float*)d_in[13];
    float* out = (float*)d_out;

    __half *wq, *xq, *aq;
    float* qkv;
    cudaGetSymbolAddress((void**)&wq, g_w);
    cudaGetSymbolAddress((void**)&xq, g_x);
    cudaGetSymbolAddress((void**)&aq, g_a);
    cudaGetSymbolAddress((void**)&qkv, g_qkv);

    cudaFuncSetAttribute(gemm_f16<0>, cudaFuncAttributeMaxDynamicSharedMemorySize, SMEM_BYTES);
    cudaFuncSetAttribute(gemm_f16<1>, cudaFuncAttributeMaxDynamicSharedMemorySize, SMEM_BYTES);
    cudaFuncSetAttribute(gemm_f16<2>, cudaFuncAttributeMaxDynamicSharedMemorySize, SMEM_BYTES);
    cudaFuncSetAttribute(attn_hmma, cudaFuncAttributeMaxDynamicSharedMemorySize, ATTN_SMEM);

    const size_t OFF_INW = 0;
    const size_t OFF_OUTW = 3145728;
    const size_t OFF_W1 = 4194304;
    const size_t OFF_W2 = 8388608;

    cvt_f16<<<(3145728 / 4 + 255) / 256, 256>>>(in_w, wq + OFF_INW, 3145728 / 4);
    cvt_f16<<<(1048576 / 4 + 255) / 256, 256>>>(out_w, wq + OFF_OUTW, 1048576 / 4);
    cvt_f16<<<(4194304 / 4 + 255) / 256, 256>>>(w1, wq + OFF_W1, 4194304 / 4);
    cvt_f16<<<(4194304 / 4 + 255) / 256, 256>>>(w2, wq + OFF_W2, 4194304 / 4);

    // 1. xn = LN1(x) -> fp16
    ln_f16<<<MROWS, 256>>>(x, ln1w, ln1b, xq);
    // 2. qkv = xn @ in_proj_w^T + b (fp32 out)
    gemm_f16<0><<<dim3(QKVD / 256, MROWS / 128), 256, SMEM_BYTES>>>(
        xq, wq + OFF_INW, in_b, nullptr, qkv, nullptr, QKVD, DM);
    // 3. attention (HMMA flash) -> fp16
    attn_hmma<<<dim3(SEQ / QT, NH, BSZ), 256, ATTN_SMEM>>>(qkv, rel_bias, xq);
    // 4. out = x + attn @ out_w^T + b
    gemm_f16<2><<<dim3(DM / 256, MROWS / 128), 256, SMEM_BYTES>>>(
        xq, wq + OFF_OUTW, out_b, x, out, nullptr, DM, DM);
    // 5. xn = LN2(out) -> fp16
    ln_f16<<<MROWS, 256>>>(out, ln2w, ln2b, xq);
    // 6. ffn = gelu(xn @ w1^T + b1) -> fp16
    gemm_f16<1><<<dim3(DFF / 256, MROWS / 128), 256, SMEM_BYTES>>>(
        xq, wq + OFF_W1, b1, nullptr, nullptr, aq, DFF, DM);
    // 7. out = out + ffn @ w2^T + b2
    gemm_f16<2><<<dim3(DM / 256, MROWS / 128), 256, SMEM_BYTES>>>(
        aq, wq + OFF_W2, b2, out, out, nullptr, DM, DFF);
}